// round 12
// baseline (speedup 1.0000x reference)
#include <cuda_runtime.h>
#include <cuda_fp16.h>
#include <math.h>

// ---------------------------------------------------------------------------
// FourierTransformLayer: out = real(ifft2( fft2(x) * W )),
//   W[c,k1,k2] = mask((k1+256)&511,(k2+256)&511) * param[c,...] / 512^2
//
// Real-input packing: two same-channel images a,b packed z = a + i*b (W real,
// conjugate-symmetric -> out_a = Re, out_b = Im). 48 complex planes.
// Register-resident radix-8 FFTs (512 = 8^3): 64 threads/FFT, 8 complex per
// thread, 2 smem exchanges. Forward DIF -> digit-reversed order; weights baked
// in that layout; inverse DIT consumes it. Spectrum stored as half2.
//
// R11: global twiddle table (no per-thread sincospif, no smem LUT), XOR
// swizzle XMAP (conflict-free for all 3 exchange patterns, keeps 8-blocks
// contiguous for float4 LDS/STS), redundant __syncthreads removed.
// ---------------------------------------------------------------------------

#define N      512
#define HALF   256
#define NPK    48            // packed planes (96 real planes / 2)
#define PLANE  (N * N)
// XOR swizzle: bijective on [0,512), conflict-free for stride-64 / stride-8 /
// contiguous-8 accesses, preserves 8-element contiguity (64B-aligned blocks).
#define XMAP(p) ((p) ^ (((p) >> 6) << 3))

__device__ unsigned g_spec[(size_t)NPK * PLANE];  // half2 per element, 48 MB
__device__ float    g_wbr[3 * PLANE];             // weights, digit-reversed layout
__device__ float2   g_lut[N];                     // exp(-2*pi*i*k/512)

__device__ __forceinline__ unsigned pack_h2(float2 a) {
    __half2 h = __floats2half2_rn(a.x, a.y);
    return *reinterpret_cast<unsigned*>(&h);
}
__device__ __forceinline__ float2 unpack_h2(unsigned u) {
    __half2 h = *reinterpret_cast<__half2*>(&u);
    return __half22float2(h);
}

// ---- packed f32x2 complex add/sub/scale ----
__device__ __forceinline__ float2 cadd(float2 a, float2 b) {
    float2 r;
    asm("{\n\t.reg .b64 ra, rb, rr;\n\t"
        "mov.b64 ra, {%2, %3};\n\t"
        "mov.b64 rb, {%4, %5};\n\t"
        "add.rn.f32x2 rr, ra, rb;\n\t"
        "mov.b64 {%0, %1}, rr;\n\t}"
        : "=f"(r.x), "=f"(r.y)
        : "f"(a.x), "f"(a.y), "f"(b.x), "f"(b.y));
    return r;
}
__device__ __forceinline__ float2 csub(float2 a, float2 b) {
    float2 r;
    asm("{\n\t.reg .b64 ra, rb, rr;\n\t"
        "mov.b64 ra, {%2, %3};\n\t"
        "mov.b64 rb, {%4, %5};\n\t"
        "sub.rn.f32x2 rr, ra, rb;\n\t"
        "mov.b64 {%0, %1}, rr;\n\t}"
        : "=f"(r.x), "=f"(r.y)
        : "f"(a.x), "f"(a.y), "f"(b.x), "f"(b.y));
    return r;
}
__device__ __forceinline__ float2 cscale(float2 a, float w) {
    float2 r;
    asm("{\n\t.reg .b64 ra, rb, rr;\n\t"
        "mov.b64 ra, {%2, %3};\n\t"
        "mov.b64 rb, {%4, %4};\n\t"
        "mul.rn.f32x2 rr, ra, rb;\n\t"
        "mov.b64 {%0, %1}, rr;\n\t}"
        : "=f"(r.x), "=f"(r.y)
        : "f"(a.x), "f"(a.y), "f"(w));
    return r;
}

__device__ __forceinline__ float2 cmul(float2 a, float2 b) {
    return make_float2(a.x * b.x - a.y * b.y, a.x * b.y + a.y * b.x);
}
// a * conj(b)
__device__ __forceinline__ float2 cmulc(float2 a, float2 b) {
    return make_float2(a.x * b.x + a.y * b.y, a.y * b.x - a.x * b.y);
}

// 8-point DFT, natural order in AND out. INV -> conjugate twiddles (unnormalized).
template<bool INV>
__device__ __forceinline__ void dft8(float2 v[8]) {
    const float s = 0.70710678118654752440f;
    float2 b0 = cadd(v[0], v[4]), t4 = csub(v[0], v[4]);
    float2 b1 = cadd(v[1], v[5]), t5 = csub(v[1], v[5]);
    float2 b2 = cadd(v[2], v[6]), t6 = csub(v[2], v[6]);
    float2 b3 = cadd(v[3], v[7]), t7 = csub(v[3], v[7]);
    float2 b4 = t4;
    float2 b5 = INV ? make_float2(s * (t5.x - t5.y), s * (t5.x + t5.y))
                    : make_float2(s * (t5.x + t5.y), s * (t5.y - t5.x));
    float2 b6 = INV ? make_float2(-t6.y, t6.x)
                    : make_float2(t6.y, -t6.x);
    float2 b7 = INV ? make_float2(-s * (t7.x + t7.y), s * (t7.x - t7.y))
                    : make_float2(s * (t7.y - t7.x), -s * (t7.x + t7.y));
    float2 c0 = cadd(b0, b2), u2 = csub(b0, b2);
    float2 c1 = cadd(b1, b3), u3 = csub(b1, b3);
    float2 c4 = cadd(b4, b6), u6 = csub(b4, b6);
    float2 c5 = cadd(b5, b7), u7 = csub(b5, b7);
    float2 c2 = u2;
    float2 c3 = INV ? make_float2(-u3.y, u3.x) : make_float2(u3.y, -u3.x);
    float2 c6 = u6;
    float2 c7 = INV ? make_float2(-u7.y, u7.x) : make_float2(u7.y, -u7.x);
    v[0] = cadd(c0, c1); v[4] = csub(c0, c1);
    v[2] = cadd(c2, c3); v[6] = csub(c2, c3);
    v[1] = cadd(c4, c5); v[5] = csub(c4, c5);
    v[3] = cadd(c6, c7); v[7] = csub(c6, c7);
}

// Sequential power chain: v[r] *= w1^r
__device__ __forceinline__ void twiddle_out(float2 v[8], float2 w1) {
    float2 w = w1;
    v[1] = cmul(v[1], w);
    #pragma unroll
    for (int r = 2; r < 8; ++r) {
        w = cmul(w, w1);
        v[r] = cmul(v[r], w);
    }
}

// v[q] *= conj(w1^q)
__device__ __forceinline__ void twiddle_in_conj(float2 v[8], float2 w1) {
    float2 w = w1;
    v[1] = cmulc(v[1], w);
    #pragma unroll
    for (int r = 2; r < 8; ++r) {
        w = cmul(w, w1);
        v[r] = cmulc(v[r], w);
    }
}

// ---------------------------------------------------------------------------
// Weight table (base-8 digit-reversed layout) + twiddle LUT.
// ---------------------------------------------------------------------------
__device__ __forceinline__ int octrev9(int p) {
    return ((p & 7) << 6) | (p & 56) | ((p >> 6) & 7);
}

__global__ void k_weights(const float* __restrict__ param) {
    int idx = blockIdx.x * blockDim.x + threadIdx.x;
    if (idx < N) {
        float s, c;
        sincospif(-(float)idx * (1.0f / 256.0f), &s, &c);
        g_lut[idx] = make_float2(c, s);
    }
    if (idx >= 3 * PLANE) return;
    int c   = idx >> 18;
    int rem = idx & (PLANE - 1);
    int k1  = octrev9(rem >> 9);
    int k2  = octrev9(rem & (N - 1));
    int sh  = (k1 + HALF) & (N - 1);
    int sw  = (k2 + HALF) & (N - 1);

    float dh = fabsf((float)(sh - HALF));
    float dw = fabsf((float)(sw - HALF));
    float r2 = dh * dh + dw * dw;
    float mval;
    if (r2 <= 1.0f) {
        mval = 0.5f;                               // SMOOTHNESS
    } else {
        float dist = sqrtf(r2) * (1.0f / 256.0f);
        mval = fmaxf(1.0f, dist * 2.0f);           // dist / SMOOTHNESS
    }
    float pv = param[c * PLANE + sh * N + sw];
    g_wbr[idx] = mval * pv * (1.0f / (float)PLANE);
}

// ---------------------------------------------------------------------------
// Row forward FFT (radix-8 DIF) on packed planes z = a + i*b.
// 4 rows/block (256 threads). Output digit-reversed as half2.
// ---------------------------------------------------------------------------
__global__ void __launch_bounds__(256, 6) k_row_fwd(const float* __restrict__ x) {
    __shared__ float2 S[4 * N];

    int tid = threadIdx.x;
    int rl = tid >> 6;
    int t  = tid & 63;
    float2* Sr = S + (rl << 9);

    int prow = blockIdx.x * 4 + rl;
    int pi   = prow >> 9;
    int r    = prow & (N - 1);
    int bp   = pi / 3;
    int ch   = pi - 3 * bp;
    const float* xre = x + (size_t)(6 * bp + ch) * PLANE + (size_t)r * N;
    const float* xim = xre + (size_t)3 * PLANE;
    int h64 = (t >> 3) << 6;
    int j8  = t & 7;

    float2 v[8];
    #pragma unroll
    for (int q = 0; q < 8; ++q) {
        int p = t + (q << 6);
        v[q] = make_float2(xre[p], xim[p]);
    }

    // stage m=64 (j = t)
    dft8<false>(v);
    twiddle_out(v, __ldg(&g_lut[t]));
    #pragma unroll
    for (int r8 = 0; r8 < 8; ++r8) Sr[XMAP(t + (r8 << 6))] = v[r8];
    __syncthreads();
    #pragma unroll
    for (int q = 0; q < 8; ++q) v[q] = Sr[XMAP(h64 + j8 + (q << 3))];

    // stage m=8 (j = t&7); store set == just-read set -> no sync needed between
    dft8<false>(v);
    twiddle_out(v, __ldg(&g_lut[j8 << 3]));
    #pragma unroll
    for (int r8 = 0; r8 < 8; ++r8) Sr[XMAP(h64 + j8 + (r8 << 3))] = v[r8];
    __syncthreads();

    // contiguous read of positions 8t..8t+7 (XMAP keeps them contiguous, 64B aligned)
    {
        const float4* Sv = (const float4*)Sr;
        int b4 = (t ^ (t >> 3)) << 2;
        float4 f0 = Sv[b4], f1 = Sv[b4 + 1], f2 = Sv[b4 + 2], f3 = Sv[b4 + 3];
        v[0] = make_float2(f0.x, f0.y); v[1] = make_float2(f0.z, f0.w);
        v[2] = make_float2(f1.x, f1.y); v[3] = make_float2(f1.z, f1.w);
        v[4] = make_float2(f2.x, f2.y); v[5] = make_float2(f2.z, f2.w);
        v[6] = make_float2(f3.x, f3.y); v[7] = make_float2(f3.z, f3.w);
    }

    // stage m=1
    dft8<false>(v);

    uint4* o = (uint4*)(g_spec + (size_t)prow * N + (t << 3));
    o[0] = make_uint4(pack_h2(v[0]), pack_h2(v[1]), pack_h2(v[2]), pack_h2(v[3]));
    o[1] = make_uint4(pack_h2(v[4]), pack_h2(v[5]), pack_h2(v[6]), pack_h2(v[7]));
}

// ---------------------------------------------------------------------------
// Fused column pass: fwd radix-8 DIF -> real weight multiply -> inv radix-8 DIT.
// Block = 8 columns of one packed plane; c = tid&7, u = tid>>3.
// ---------------------------------------------------------------------------
__global__ void __launch_bounds__(512, 3) k_col_fused() {
    __shared__ float2 S[N * 8];

    int tid  = threadIdx.x;
    int c    = tid & 7;
    int u    = tid >> 3;
    int img  = blockIdx.x >> 6;          // 0..47
    int col0 = (blockIdx.x & 63) << 3;
    int ch   = img % 3;

    unsigned* base = g_spec + (size_t)img * PLANE + col0 + c;
    int h64 = (u >> 3) << 6;
    int j8  = u & 7;

    float2 v[8];
    #pragma unroll
    for (int q = 0; q < 8; ++q) v[q] = unpack_h2(base[(size_t)(u + (q << 6)) * N]);

    // ---- forward: stage m=64 ----
    dft8<false>(v);
    twiddle_out(v, __ldg(&g_lut[u]));
    #pragma unroll
    for (int r = 0; r < 8; ++r) S[(XMAP(u + (r << 6)) << 3) | c] = v[r];
    __syncthreads();
    #pragma unroll
    for (int q = 0; q < 8; ++q) v[q] = S[(XMAP(h64 + j8 + (q << 3)) << 3) | c];

    // ---- forward: stage m=8 (store set == read set: no intervening sync) ----
    dft8<false>(v);
    twiddle_out(v, __ldg(&g_lut[j8 << 3]));
    #pragma unroll
    for (int r = 0; r < 8; ++r) S[(XMAP(h64 + j8 + (r << 3)) << 3) | c] = v[r];
    __syncthreads();
    #pragma unroll
    for (int q = 0; q < 8; ++q) v[q] = S[(XMAP((u << 3) + q) << 3) | c];

    // ---- forward m=1 -> weight -> inverse m=1, all in registers ----
    dft8<false>(v);
    const float* wp = g_wbr + (size_t)ch * PLANE + (size_t)(u << 3) * N + col0 + c;
    #pragma unroll
    for (int r = 0; r < 8; ++r) v[r] = cscale(v[r], wp[(size_t)r * N]);
    dft8<true>(v);

    // store back to own contiguous set (same addresses just read: no sync needed)
    #pragma unroll
    for (int r = 0; r < 8; ++r) S[(XMAP((u << 3) + r) << 3) | c] = v[r];
    __syncthreads();
    #pragma unroll
    for (int q = 0; q < 8; ++q) v[q] = S[(XMAP(h64 + j8 + (q << 3)) << 3) | c];

    // ---- inverse: stage m=8 (store set == read set) ----
    twiddle_in_conj(v, __ldg(&g_lut[j8 << 3]));
    dft8<true>(v);
    #pragma unroll
    for (int r = 0; r < 8; ++r) S[(XMAP(h64 + j8 + (r << 3)) << 3) | c] = v[r];
    __syncthreads();
    #pragma unroll
    for (int q = 0; q < 8; ++q) v[q] = S[(XMAP(u + (q << 6)) << 3) | c];

    // ---- inverse: stage m=64 ----
    twiddle_in_conj(v, __ldg(&g_lut[u]));
    dft8<true>(v);
    #pragma unroll
    for (int r = 0; r < 8; ++r) base[(size_t)(u + (r << 6)) * N] = pack_h2(v[r]);
}

// ---------------------------------------------------------------------------
// Row inverse FFT (radix-8 DIT, digit-reversed half2 input -> natural).
// 4 rows/block (256 threads). out_a = Re, out_b = Im, coalesced real stores.
// ---------------------------------------------------------------------------
__global__ void __launch_bounds__(256, 6) k_row_inv(float* __restrict__ out) {
    __shared__ float2 S[4 * N];

    int tid = threadIdx.x;
    int rl = tid >> 6;
    int t  = tid & 63;
    float2* Sr = S + (rl << 9);

    int prow = blockIdx.x * 4 + rl;
    int pi   = prow >> 9;
    int r    = prow & (N - 1);
    int bp   = pi / 3;
    int ch   = pi - 3 * bp;
    int h64  = (t >> 3) << 6;
    int j8   = t & 7;

    const uint4* in4 = (const uint4*)(g_spec + (size_t)prow * N + (t << 3));
    float2 v[8];
    {
        uint4 a0 = in4[0], a1 = in4[1];
        v[0] = unpack_h2(a0.x); v[1] = unpack_h2(a0.y);
        v[2] = unpack_h2(a0.z); v[3] = unpack_h2(a0.w);
        v[4] = unpack_h2(a1.x); v[5] = unpack_h2(a1.y);
        v[6] = unpack_h2(a1.z); v[7] = unpack_h2(a1.w);
    }

    // stage m=1; store contiguous 8t..8t+7 via float4 (XMAP-contiguous, 64B aligned)
    dft8<true>(v);
    {
        float4* Sv = (float4*)Sr;
        int b4 = (t ^ (t >> 3)) << 2;
        Sv[b4]     = make_float4(v[0].x, v[0].y, v[1].x, v[1].y);
        Sv[b4 + 1] = make_float4(v[2].x, v[2].y, v[3].x, v[3].y);
        Sv[b4 + 2] = make_float4(v[4].x, v[4].y, v[5].x, v[5].y);
        Sv[b4 + 3] = make_float4(v[6].x, v[6].y, v[7].x, v[7].y);
    }
    __syncthreads();
    #pragma unroll
    for (int q = 0; q < 8; ++q) v[q] = Sr[XMAP(h64 + j8 + (q << 3))];

    // stage m=8 (store set == read set: no intervening sync)
    twiddle_in_conj(v, __ldg(&g_lut[j8 << 3]));
    dft8<true>(v);
    #pragma unroll
    for (int r8 = 0; r8 < 8; ++r8) Sr[XMAP(h64 + j8 + (r8 << 3))] = v[r8];
    __syncthreads();
    #pragma unroll
    for (int q = 0; q < 8; ++q) v[q] = Sr[XMAP(t + (q << 6))];

    // stage m=64
    twiddle_in_conj(v, __ldg(&g_lut[t]));
    dft8<true>(v);

    float* ore = out + (size_t)(6 * bp + ch) * PLANE + (size_t)r * N;
    float* oim = ore + (size_t)3 * PLANE;
    #pragma unroll
    for (int r8 = 0; r8 < 8; ++r8) {
        int p = t + (r8 << 6);
        ore[p] = v[r8].x;
        oim[p] = v[r8].y;
    }
}

// ---------------------------------------------------------------------------
extern "C" void kernel_launch(void* const* d_in, const int* in_sizes, int n_in,
                              void* d_out, int out_size) {
    const float* x = (const float*)d_in[0];
    const float* p = (const float*)d_in[1];
    if (n_in >= 2 && in_sizes[0] < in_sizes[1]) { const float* t = x; x = p; p = t; }
    float* out = (float*)d_out;

    k_weights<<<(3 * PLANE + 255) / 256, 256>>>(p);
    k_row_fwd<<<NPK * N / 4, 256>>>(x);
    k_col_fused<<<NPK * (N / 8), 512>>>();
    k_row_inv<<<NPK * N / 4, 256>>>(out);
}